// round 4
// baseline (speedup 1.0000x reference)
#include <cuda_runtime.h>
#include <cuda_fp16.h>
#include <cstdint>
#include <cstddef>

// ---------------------------------------------------------------------------
// Problem constants
// ---------------------------------------------------------------------------
#define HIDDEN   768
#define META     25
#define ED_COUNT 300
#define BATCH    2
#define N_MENT   2000
#define N_PAIRS  40000
#define M_TOTAL  (BATCH * N_MENT)        // 4000
#define N_TOTAL  (2 * HIDDEN)            // 1536
#define P_TOTAL  (BATCH * N_PAIRS)       // 80000

// ---------------------------------------------------------------------------
// Device scratch (fp16 storage: halves pair-kernel L2 traffic)
// ---------------------------------------------------------------------------
__device__ __half g_ACh[(size_t)M_TOTAL * N_TOTAL];   // 12.3 MB
__device__ __half g_Eh[(size_t)ED_COUNT * HIDDEN];    // 0.46 MB

// ---------------------------------------------------------------------------
// tf32 mma.sync GEMM, block 128x128x16, 256 thr, warp tile 64x32, 2-stage
// ---------------------------------------------------------------------------
#define BK        16
#define NSTAGE    48                 // 768 / 16
#define A_STRIDE  20
#define B_STRIDE  136

__device__ __forceinline__ uint32_t smem_u32(const void* p) {
    uint32_t a;
    asm("{ .reg .u64 t; cvta.to.shared.u64 t, %1; cvt.u32.u64 %0, t; }" : "=r"(a) : "l"(p));
    return a;
}
__device__ __forceinline__ void cp_async16(uint32_t dst, const void* src, uint32_t src_bytes) {
    asm volatile("cp.async.ca.shared.global [%0], [%1], 16, %2;"
                 :: "r"(dst), "l"(src), "r"(src_bytes) : "memory");
}
__device__ __forceinline__ uint32_t f2tf32(float f) {
    uint32_t u;
    asm("cvt.rna.tf32.f32 %0, %1;" : "=r"(u) : "f"(f));
    return u;
}
__device__ __forceinline__ void mma_tf32(float* c, const uint32_t* a, const uint32_t* b) {
    asm volatile(
        "mma.sync.aligned.m16n8k8.row.col.f32.tf32.tf32.f32 "
        "{%0,%1,%2,%3}, {%4,%5,%6,%7}, {%8,%9}, {%0,%1,%2,%3};"
        : "+f"(c[0]), "+f"(c[1]), "+f"(c[2]), "+f"(c[3])
        : "r"(a[0]), "r"(a[1]), "r"(a[2]), "r"(a[3]), "r"(b[0]), "r"(b[1]));
}

__global__ __launch_bounds__(256)
void gemm_tc_kernel(const float* __restrict__ A,      // [4000,768]
                    const float* __restrict__ W1)     // [1561,768]
{
    __shared__ __align__(16) float As[2][128 * A_STRIDE];
    __shared__ __align__(16) float Bs[2][BK * B_STRIDE];

    const int tid  = threadIdx.x;
    const int wid  = tid >> 5;
    const int lane = tid & 31;
    const int gid  = lane >> 2;
    const int tig  = lane & 3;

    const int nbase = blockIdx.x * 128;
    const int mbase = blockIdx.y * 128;
    const int half  = nbase >= HIDDEN;
    const int nloc  = nbase - half * HIDDEN;
    const float* Bsrc = W1 + (size_t)half * HIDDEN * HIDDEN + nloc;

    const int wm = (wid >> 2) * 64;
    const int wn = (wid & 3) * 32;

    const int a_row = tid >> 1;
    const int a_q0  = (tid & 1) * 2;
    const int a_gm  = mbase + a_row;
    const uint32_t a_bytes = (a_gm < M_TOTAL) ? 16u : 0u;
    const float* a_src_base = A + (size_t)a_gm * HIDDEN;
    const uint32_t a_dst_base0 = smem_u32(&As[0][a_row * A_STRIDE]);
    const uint32_t a_dst_base1 = smem_u32(&As[1][a_row * A_STRIDE]);
    const int b_c0_row = tid >> 5,         b_c0_col = (tid & 31) * 4;
    const int b_c1_row = (tid + 256) >> 5, b_c1_col = ((tid + 256) & 31) * 4;
    const uint32_t b_dst0_s0 = smem_u32(&Bs[0][b_c0_row * B_STRIDE + b_c0_col]);
    const uint32_t b_dst1_s0 = smem_u32(&Bs[0][b_c1_row * B_STRIDE + b_c1_col]);
    const uint32_t b_dst0_s1 = smem_u32(&Bs[1][b_c0_row * B_STRIDE + b_c0_col]);
    const uint32_t b_dst1_s1 = smem_u32(&Bs[1][b_c1_row * B_STRIDE + b_c1_col]);

    float acc[4][4][4];
#pragma unroll
    for (int mt = 0; mt < 4; mt++)
#pragma unroll
        for (int nt = 0; nt < 4; nt++)
#pragma unroll
            for (int r = 0; r < 4; r++) acc[mt][nt][r] = 0.f;

    auto load_stage = [&](int kc) {
        const int buf = kc & 1;
        const int k0 = kc * BK;
        const uint32_t adst = buf ? a_dst_base1 : a_dst_base0;
        cp_async16(adst + (a_q0 + 0) * 16, a_src_base + k0 + (a_q0 + 0) * 4, a_bytes);
        cp_async16(adst + (a_q0 + 1) * 16, a_src_base + k0 + (a_q0 + 1) * 4, a_bytes);
        cp_async16(buf ? b_dst0_s1 : b_dst0_s0,
                   Bsrc + (size_t)(k0 + b_c0_row) * HIDDEN + b_c0_col, 16u);
        cp_async16(buf ? b_dst1_s1 : b_dst1_s0,
                   Bsrc + (size_t)(k0 + b_c1_row) * HIDDEN + b_c1_col, 16u);
        asm volatile("cp.async.commit_group;" ::: "memory");
    };

    load_stage(0);

    for (int kc = 0; kc < NSTAGE; kc++) {
        if (kc + 1 < NSTAGE) {
            load_stage(kc + 1);
            asm volatile("cp.async.wait_group 1;" ::: "memory");
        } else {
            asm volatile("cp.async.wait_group 0;" ::: "memory");
        }
        __syncthreads();

        const int buf = kc & 1;
        const float* as = As[buf];
        const float* bs = Bs[buf];
#pragma unroll
        for (int ks = 0; ks < 2; ks++) {
            const int kk = ks * 8;
            uint32_t af[4][4], bf[4][2];
#pragma unroll
            for (int mt = 0; mt < 4; mt++) {
                const float* ap = as + (wm + mt * 16 + gid) * A_STRIDE + kk + tig;
                af[mt][0] = f2tf32(ap[0]);
                af[mt][1] = f2tf32(ap[8 * A_STRIDE]);
                af[mt][2] = f2tf32(ap[4]);
                af[mt][3] = f2tf32(ap[8 * A_STRIDE + 4]);
            }
#pragma unroll
            for (int nt = 0; nt < 4; nt++) {
                const float* bp = bs + (kk + tig) * B_STRIDE + wn + nt * 8 + gid;
                bf[nt][0] = f2tf32(bp[0]);
                bf[nt][1] = f2tf32(bp[4 * B_STRIDE]);
            }
#pragma unroll
            for (int mt = 0; mt < 4; mt++)
#pragma unroll
                for (int nt = 0; nt < 4; nt++)
                    mma_tf32(acc[mt][nt], af[mt], bf[nt]);
        }
        __syncthreads();
    }

    // -------- epilogue: convert to fp16, write half2 --------
#pragma unroll
    for (int mt = 0; mt < 4; mt++) {
        const int m0 = mbase + wm + mt * 16 + gid;
#pragma unroll
        for (int nt = 0; nt < 4; nt++) {
            const int n0 = nbase + wn + nt * 8 + 2 * tig;
            if (m0 < M_TOTAL)
                *(__half2*)(g_ACh + (size_t)m0 * N_TOTAL + n0)
                    = __floats2half2_rn(acc[mt][nt][0], acc[mt][nt][1]);
            if (m0 + 8 < M_TOTAL)
                *(__half2*)(g_ACh + (size_t)(m0 + 8) * N_TOTAL + n0)
                    = __floats2half2_rn(acc[mt][nt][2], acc[mt][nt][3]);
        }
    }
}

// ---------------------------------------------------------------------------
// ed kernel, j-tiled: 24 blocks x 128 thr; smem-cached ed_table + W1 slice.
// E[e][j] = b1[j] + sum_t ed_table[e][t] * W1[1536+t][j]
// ---------------------------------------------------------------------------
#define ED_JTILE 32

__global__ __launch_bounds__(128)
void ed_kernel(const float* __restrict__ ed_table,
               const float* __restrict__ W1,
               const float* __restrict__ b1)
{
    __shared__ float s_ed[ED_COUNT * META];        // 30 KB
    __shared__ float s_w[META * ED_JTILE];         // 3.2 KB
    const int tid = threadIdx.x;
    const int jbase = blockIdx.x * ED_JTILE;

    for (int i = tid; i < ED_COUNT * META; i += 128) s_ed[i] = ed_table[i];
    for (int i = tid; i < META * ED_JTILE; i += 128) {
        const int t = i / ED_JTILE, j = i % ED_JTILE;
        s_w[i] = W1[(size_t)(2 * HIDDEN + t) * HIDDEN + jbase + j];
    }
    __syncthreads();

    const int jcol = tid & 31;                     // 0..31
    const int erow0 = tid >> 5;                    // 0..3
    const float bias = b1[jbase + jcol];
    for (int e = erow0; e < ED_COUNT; e += 4) {
        float s = bias;
        const float* ed = s_ed + e * META;
#pragma unroll
        for (int t = 0; t < META; t++)
            s = fmaf(ed[t], s_w[t * ED_JTILE + jcol], s);
        g_Eh[(size_t)e * HIDDEN + jbase + jcol] = __float2half_rn(s);
    }
}

// ---------------------------------------------------------------------------
// pair kernel: logit = b2 + sum_j relu(A[i1][j]+C[i2][j]+E[ed][j]) * W2[j]
// fp16 rows (uint4 = 8 halves), fp32 math, warp/pair.
// ---------------------------------------------------------------------------
__device__ __forceinline__ float2 h2f(uint32_t u) {
    __half2 h = *reinterpret_cast<__half2*>(&u);
    return __half22float2(h);
}

__global__ __launch_bounds__(256)
void pair_kernel(const int*   __restrict__ pairs,
                 const int*   __restrict__ eds,
                 const float* __restrict__ W2,
                 const float* __restrict__ b2,
                 float*       __restrict__ out)
{
    const int p = blockIdx.x * 8 + (threadIdx.x >> 5);
    if (p >= P_TOTAL) return;
    const int lane = threadIdx.x & 31;

    const int b  = p / N_PAIRS;
    const int i1 = pairs[2 * p];
    const int i2 = pairs[2 * p + 1];
    const int ed = eds[p];

    const uint4* Arow = (const uint4*)(g_ACh + (size_t)(b * N_MENT + i1) * N_TOTAL);
    const uint4* Crow = (const uint4*)(g_ACh + (size_t)(b * N_MENT + i2) * N_TOTAL + HIDDEN);
    const uint4* Erow = (const uint4*)(g_Eh  + (size_t)ed * HIDDEN);
    const float4* Wrow = (const float4*)W2;

    float acc = 0.f;
#pragma unroll
    for (int i = 0; i < HIDDEN / 8 / 32; i++) {    // 3 iterations, 8 halves each
        const int idx = lane + i * 32;
        uint4 a = Arow[idx];
        uint4 c = Crow[idx];
        uint4 e = Erow[idx];
        float4 w0 = Wrow[2 * idx];
        float4 w1 = Wrow[2 * idx + 1];
        float2 fa, fc, fe;
        float h;
        fa = h2f(a.x); fc = h2f(c.x); fe = h2f(e.x);
        h = fa.x + fc.x + fe.x; if (h > 0.f) acc = fmaf(h, w0.x, acc);
        h = fa.y + fc.y + fe.y; if (h > 0.f) acc = fmaf(h, w0.y, acc);
        fa = h2f(a.y); fc = h2f(c.y); fe = h2f(e.y);
        h = fa.x + fc.x + fe.x; if (h > 0.f) acc = fmaf(h, w0.z, acc);
        h = fa.y + fc.y + fe.y; if (h > 0.f) acc = fmaf(h, w0.w, acc);
        fa = h2f(a.z); fc = h2f(c.z); fe = h2f(e.z);
        h = fa.x + fc.x + fe.x; if (h > 0.f) acc = fmaf(h, w1.x, acc);
        h = fa.y + fc.y + fe.y; if (h > 0.f) acc = fmaf(h, w1.y, acc);
        fa = h2f(a.w); fc = h2f(c.w); fe = h2f(e.w);
        h = fa.x + fc.x + fe.x; if (h > 0.f) acc = fmaf(h, w1.z, acc);
        h = fa.y + fc.y + fe.y; if (h > 0.f) acc = fmaf(h, w1.w, acc);
    }
#pragma unroll
    for (int off = 16; off; off >>= 1)
        acc += __shfl_xor_sync(0xffffffffu, acc, off);
    if (lane == 0) out[p] = acc + b2[0];
}

// ---------------------------------------------------------------------------
// Launch
// ---------------------------------------------------------------------------
extern "C" void kernel_launch(void* const* d_in, const int* in_sizes, int n_in,
                              void* d_out, int out_size)
{
    const float* mention  = (const float*)d_in[0];
    const int*   pairs    = (const int*)  d_in[1];
    const int*   eds      = (const int*)  d_in[2];
    const float* ed_table = (const float*)d_in[3];
    const float* W1       = (const float*)d_in[4];
    const float* b1       = (const float*)d_in[5];
    const float* W2       = (const float*)d_in[6];
    const float* b2       = (const float*)d_in[7];
    float* out = (float*)d_out;
    (void)in_sizes; (void)n_in; (void)out_size;

    {
        dim3 g(N_TOTAL / 128, (M_TOTAL + 127) / 128);   // (12, 32)
        gemm_tc_kernel<<<g, 256>>>(mention, W1);
    }
    ed_kernel<<<HIDDEN / ED_JTILE, 128>>>(ed_table, W1, b1);   // 24 blocks
    pair_kernel<<<(P_TOTAL + 7) / 8, 256>>>(pairs, eds, W2, b2, out);
}